// round 15
// baseline (speedup 1.0000x reference)
#include <cuda_runtime.h>
#include <cuda_fp16.h>
#include <cstdint>
#include <cstddef>

// ---------------------------------------------------------------------------
// VenomSpmm: y = x @ (W * mask).T + bias, mask keeps k%8 in {0,2}.
// K 4096 -> 1024 packed fp16. fp16-ACCUMULATE mma.sync (2x HMMA rate) with
// per-BK64-chunk promotion to fp32 (error ~3e-4, under the 1e-3 gate).
// CTA 128x128, warp tile 64x32 processed in two mi-halves (reg budget),
// BK=64, 3-stage cp.async ring, 96KB smem, 2 CTAs/SM.
// ---------------------------------------------------------------------------

static constexpr int MAX_M  = 16384;
static constexpr int MAX_N  = 4096;
static constexpr int MAX_KP = 1024;

__device__ __half g_xp[(size_t)MAX_M * MAX_KP];   // 32 MB
__device__ __half g_wp[(size_t)MAX_N * MAX_KP];   // 8 MB

// ---------------------------------------------------------------------------
// Combined pack kernel: keep positions 0,2 of every 8 along K, fp32->fp16.
// ---------------------------------------------------------------------------
__global__ void pack_xw(const float* __restrict__ xs, const float* __restrict__ ws,
                        long long total_x, long long total, int kd) {
    long long idx = (long long)blockIdx.x * blockDim.x + threadIdx.x;
    if (idx >= total) return;
    int gpr = kd >> 3;
    const float* src;
    __half* dst;
    long long lidx;
    if (idx < total_x) { src = xs; dst = g_xp; lidx = idx; }
    else               { src = ws; dst = g_wp; lidx = idx - total_x; }
    long long m = lidx / gpr;
    int g = (int)(lidx - m * (long long)gpr);
    const float* p = src + m * (long long)kd + ((long long)g << 3);
    __half2 h;
    h.x = __float2half(p[0]);
    h.y = __float2half(p[2]);
    *(__half2*)(dst + (size_t)m * (size_t)(kd >> 2) + 2 * (size_t)g) = h;
}

// ---------------------------------------------------------------------------
// PTX helpers (baseline ISA only — harness ptxas targets sm_103, no 'a')
// ---------------------------------------------------------------------------
__device__ __forceinline__ uint32_t smem_u32(const void* p) {
    uint32_t a;
    asm("{ .reg .u64 t; cvta.to.shared.u64 t, %1; cvt.u32.u64 %0, t; }"
        : "=r"(a) : "l"(p));
    return a;
}
__device__ __forceinline__ void cp_async16(uint32_t dst, const void* src) {
    asm volatile("cp.async.cg.shared.global [%0], [%1], 16;\n" :: "r"(dst), "l"(src));
}
__device__ __forceinline__ void cp_async_commit() {
    asm volatile("cp.async.commit_group;\n" ::: "memory");
}
template <int N>
__device__ __forceinline__ void cp_async_wait() {
    asm volatile("cp.async.wait_group %0;\n" :: "n"(N) : "memory");
}
__device__ __forceinline__ void ldsm_x4(uint32_t* r, uint32_t addr) {
    asm volatile("ldmatrix.sync.aligned.m8n8.x4.shared.b16 {%0,%1,%2,%3}, [%4];"
                 : "=r"(r[0]), "=r"(r[1]), "=r"(r[2]), "=r"(r[3]) : "r"(addr));
}
// fp16-accumulate MMA: 2x rate of the f32-accum form; C/D are f16x2 pairs.
__device__ __forceinline__ void mma_fp16acc(uint32_t* c, const uint32_t* a,
                                            const uint32_t* b) {
    asm volatile(
        "mma.sync.aligned.m16n8k16.row.col.f16.f16.f16.f16 "
        "{%0,%1}, {%2,%3,%4,%5}, {%6,%7}, {%0,%1};\n"
        : "+r"(c[0]), "+r"(c[1])
        : "r"(a[0]), "r"(a[1]), "r"(a[2]), "r"(a[3]), "r"(b[0]), "r"(b[1]));
}
__device__ __forceinline__ uint32_t sw128(uint32_t off) {
    return off ^ ((off >> 3) & 0x70);
}

// ---------------------------------------------------------------------------
// GEMM: out[M,N] = A*B^T + bias,  A=g_xp[M,K], B=g_wp[N,K], K=1024 (fp16)
// CTA tile 128(M) x 128(N), BK=64, 3-stage cp.async ring, 96KB smem.
// 8 warps as 2(M) x 4(N); warp tile 64x32 split into two 32x32 mi-halves.
// Per half: fp16-C chain over 4 k-steps, then promote to fp32 accumulators.
// ---------------------------------------------------------------------------
static constexpr int NSTAGES     = 3;
static constexpr int A_BYTES     = 128 * 128;          // 16 KB
static constexpr int B_BYTES     = 128 * 128;          // 16 KB
static constexpr int STAGE_BYTES = A_BYTES + B_BYTES;  // 32 KB
static constexpr int SMEM_DYN    = NSTAGES * STAGE_BYTES;   // 96 KB

__global__ __launch_bounds__(256, 2)
void gemm_fp16(const float* __restrict__ bias, float* __restrict__ out,
               int M, int N, int K) {
    extern __shared__ char smem[];
    const int tid = threadIdx.x;
    const int wid = tid >> 5;
    const int lane = tid & 31;
    const int m0 = blockIdx.x * 128;          // x -> M tiles (fast-varying)
    const int n0 = blockIdx.y * 128;          // y -> N tiles
    const uint32_t sbase = smem_u32(smem);

    const int warp_m = (wid & 1) * 64;
    const int warp_n = (wid >> 1) * 32;

    const int NUM_IT = K >> 6;                        // 16 k-tiles of 64

    // ---- async stage loader: 2048 16B-chunks over 256 threads x 8 ----------
    auto load_stage = [&](int slot, int it) {
        const uint32_t sb = sbase + slot * STAGE_BYTES;
        const int kt = it << 6;
#pragma unroll
        for (int i = 0; i < 8; i++) {
            int cid = tid + i * 256;                  // 0..2047
            int mat = cid >> 10;                      // 0:A 1:B
            int within = cid & 1023;
            int row = within >> 3;                    // 0..127
            int c16 = within & 7;
            const __half* src = (mat == 0)
                ? g_xp + (size_t)(m0 + row) * K + kt + c16 * 8
                : g_wp + (size_t)(n0 + row) * K + kt + c16 * 8;
            uint32_t off = (uint32_t)(row * 128 + c16 * 16);
            cp_async16(sb + mat * A_BYTES + sw128(off), src);
        }
        cp_async_commit();
    };

    load_stage(0, 0);
    load_stage(1, 1);

    float acc[4][4][4];                               // [mi][nj][4] fp32
#pragma unroll
    for (int i = 0; i < 4; i++)
#pragma unroll
        for (int j = 0; j < 4; j++)
#pragma unroll
            for (int r = 0; r < 4; r++) acc[i][j][r] = 0.0f;

    const int a_row = lane & 15;
    const int a_kc  = ((lane >> 4) & 1) * 8;
    const int b_row = ((lane >> 4) & 1) * 8 + (lane & 7);
    const int b_kc  = ((lane >> 3) & 1) * 8;

    for (int it = 0; it < NUM_IT; it++) {
        const int s = it % NSTAGES;
        if (it < NUM_IT - 1) cp_async_wait<NSTAGES - 2>();
        else                 cp_async_wait<0>();
        __syncthreads();

        if (it + NSTAGES - 1 < NUM_IT)
            load_stage((it + NSTAGES - 1) % NSTAGES, it + NSTAGES - 1);

        const uint32_t sA = sbase + s * STAGE_BYTES;
        const uint32_t sB = sA + A_BYTES;

        // Two mi-halves; fp16-C chain over the 4 k-steps of this BK=64 tile,
        // then promote into fp32 accumulators (bounds accumulation error).
#pragma unroll
        for (int h = 0; h < 2; h++) {
            uint32_t ch[2][4][2];                      // [mi-in-half][nj][2]
#pragma unroll
            for (int i = 0; i < 2; i++)
#pragma unroll
                for (int j = 0; j < 4; j++) { ch[i][j][0] = 0u; ch[i][j][1] = 0u; }

#pragma unroll
            for (int ks = 0; ks < 4; ks++) {
                uint32_t a[2][4], b[4][2];
#pragma unroll
                for (int mi = 0; mi < 2; mi++) {
                    int row = warp_m + (h * 2 + mi) * 16 + a_row;
                    uint32_t off = (uint32_t)(row * 128 + (ks * 16 + a_kc) * 2);
                    ldsm_x4(a[mi], sA + sw128(off));
                }
#pragma unroll
                for (int p = 0; p < 2; p++) {
                    int row = warp_n + p * 16 + b_row;
                    uint32_t off = (uint32_t)(row * 128 + (ks * 16 + b_kc) * 2);
                    uint32_t t[4];
                    ldsm_x4(t, sB + sw128(off));
                    b[p * 2 + 0][0] = t[0]; b[p * 2 + 0][1] = t[1];
                    b[p * 2 + 1][0] = t[2]; b[p * 2 + 1][1] = t[3];
                }
#pragma unroll
                for (int mi = 0; mi < 2; mi++)
#pragma unroll
                    for (int nj = 0; nj < 4; nj++)
                        mma_fp16acc(ch[mi][nj], a[mi], b[nj]);
            }

            // Promote chunk to fp32.
#pragma unroll
            for (int mi = 0; mi < 2; mi++)
#pragma unroll
                for (int nj = 0; nj < 4; nj++) {
                    float* af = acc[h * 2 + mi][nj];
                    float2 lo = __half22float2(*reinterpret_cast<__half2*>(&ch[mi][nj][0]));
                    float2 hi = __half22float2(*reinterpret_cast<__half2*>(&ch[mi][nj][1]));
                    af[0] += lo.x; af[1] += lo.y;
                    af[2] += hi.x; af[3] += hi.y;
                }
        }
    }

    // ---- epilogue: bias + global writes ------------------------------------
    const int col_base = n0 + warp_n + 2 * (lane & 3);
    const int row_base = m0 + warp_m + (lane >> 2);

#pragma unroll
    for (int nj = 0; nj < 4; nj++) {
        int c = col_base + nj * 8;
        float b0 = __ldg(bias + c);
        float b1 = __ldg(bias + c + 1);
#pragma unroll
        for (int mi = 0; mi < 4; mi++) {
            int r = row_base + mi * 16;
            float2 v0 = make_float2(acc[mi][nj][0] + b0, acc[mi][nj][1] + b1);
            float2 v1 = make_float2(acc[mi][nj][2] + b0, acc[mi][nj][3] + b1);
            *(float2*)(out + (size_t)r * N + c) = v0;
            *(float2*)(out + (size_t)(r + 8) * N + c) = v1;
        }
    }
}

// ---------------------------------------------------------------------------
// Launch
// ---------------------------------------------------------------------------
extern "C" void kernel_launch(void* const* d_in, const int* in_sizes, int n_in,
                              void* d_out, int out_size) {
    const float* x    = (const float*)d_in[0];
    const float* w    = (const float*)d_in[1];
    const float* bias = (const float*)d_in[2];
    float* out = (float*)d_out;

    const int n_out = in_sizes[2];                        // 4096
    const int kd    = in_sizes[1] / n_out;                // 4096
    const int M     = (int)((long long)in_sizes[0] / kd); // 16384
    const int Kp    = kd / 4;                             // 1024

    cudaFuncSetAttribute(gemm_fp16,
                         cudaFuncAttributeMaxDynamicSharedMemorySize, SMEM_DYN);

    {
        long long total_x = (long long)M * (kd >> 3);
        long long total = total_x + (long long)n_out * (kd >> 3);
        pack_xw<<<(int)((total + 255) / 256), 256>>>(x, w, total_x, total, kd);
    }
    {
        dim3 grid(M / 128, n_out / 128);                  // x = M tiles, y = N tiles
        gemm_fp16<<<grid, 256, SMEM_DYN>>>(bias, out, M, n_out, Kp);
    }
}

// round 16
// speedup vs baseline: 1.2489x; 1.2489x over previous
#include <cuda_runtime.h>
#include <cuda_fp16.h>
#include <cstdint>
#include <cstddef>

// ---------------------------------------------------------------------------
// VenomSpmm: y = x @ (W * mask).T + bias, mask keeps k%8 in {0,2}.
// K 4096 -> 1024 packed fp16. Single-pass fp16 GEMM (fp32 accum) on mma.sync.
// FINAL measured-best config (R14, 415.2us): CTA 128x128, warp tile 64x32,
// BK=64, 3-stage inline cp.async ring, 96KB smem, launch_bounds(256,2)
// -> 2 CTAs/SM; M-fast grid rasterization (consecutive CTAs share B tile).
// fp16-acc (R15) and warp-spec (R8/R12) variants measured slower; fp32-accum
// mma.sync at 64% tensor pipe is the harness ceiling (no tcgen05: ptxas
// targets sm_103, not sm_103a).
// ---------------------------------------------------------------------------

static constexpr int MAX_M  = 16384;
static constexpr int MAX_N  = 4096;
static constexpr int MAX_KP = 1024;

__device__ __half g_xp[(size_t)MAX_M * MAX_KP];   // 32 MB
__device__ __half g_wp[(size_t)MAX_N * MAX_KP];   // 8 MB

// ---------------------------------------------------------------------------
// Combined pack kernel: keep positions 0,2 of every 8 along K, fp32->fp16.
// ---------------------------------------------------------------------------
__global__ void pack_xw(const float* __restrict__ xs, const float* __restrict__ ws,
                        long long total_x, long long total, int kd) {
    long long idx = (long long)blockIdx.x * blockDim.x + threadIdx.x;
    if (idx >= total) return;
    int gpr = kd >> 3;
    const float* src;
    __half* dst;
    long long lidx;
    if (idx < total_x) { src = xs; dst = g_xp; lidx = idx; }
    else               { src = ws; dst = g_wp; lidx = idx - total_x; }
    long long m = lidx / gpr;
    int g = (int)(lidx - m * (long long)gpr);
    const float* p = src + m * (long long)kd + ((long long)g << 3);
    __half2 h;
    h.x = __float2half(p[0]);
    h.y = __float2half(p[2]);
    *(__half2*)(dst + (size_t)m * (size_t)(kd >> 2) + 2 * (size_t)g) = h;
}

// ---------------------------------------------------------------------------
// PTX helpers (baseline ISA only — harness ptxas targets sm_103, no 'a')
// ---------------------------------------------------------------------------
__device__ __forceinline__ uint32_t smem_u32(const void* p) {
    uint32_t a;
    asm("{ .reg .u64 t; cvta.to.shared.u64 t, %1; cvt.u32.u64 %0, t; }"
        : "=r"(a) : "l"(p));
    return a;
}
__device__ __forceinline__ void cp_async16(uint32_t dst, const void* src) {
    asm volatile("cp.async.cg.shared.global [%0], [%1], 16;\n" :: "r"(dst), "l"(src));
}
__device__ __forceinline__ void cp_async_commit() {
    asm volatile("cp.async.commit_group;\n" ::: "memory");
}
template <int N>
__device__ __forceinline__ void cp_async_wait() {
    asm volatile("cp.async.wait_group %0;\n" :: "n"(N) : "memory");
}
__device__ __forceinline__ void ldsm_x4(uint32_t* r, uint32_t addr) {
    asm volatile("ldmatrix.sync.aligned.m8n8.x4.shared.b16 {%0,%1,%2,%3}, [%4];"
                 : "=r"(r[0]), "=r"(r[1]), "=r"(r[2]), "=r"(r[3]) : "r"(addr));
}
__device__ __forceinline__ void mma_fp16(float* d, const uint32_t* a, const uint32_t* b) {
    asm volatile(
        "mma.sync.aligned.m16n8k16.row.col.f32.f16.f16.f32 "
        "{%0,%1,%2,%3}, {%4,%5,%6,%7}, {%8,%9}, {%0,%1,%2,%3};\n"
        : "+f"(d[0]), "+f"(d[1]), "+f"(d[2]), "+f"(d[3])
        : "r"(a[0]), "r"(a[1]), "r"(a[2]), "r"(a[3]), "r"(b[0]), "r"(b[1]));
}
__device__ __forceinline__ uint32_t sw128(uint32_t off) {
    return off ^ ((off >> 3) & 0x70);
}

// ---------------------------------------------------------------------------
// GEMM: out[M,N] = A*B^T + bias,  A=g_xp[M,K], B=g_wp[N,K], K=1024 (fp16)
// CTA tile 128(M) x 128(N), BK=64 (128B rows, SW128), 3-stage cp.async ring.
// 8 warps as 2(M) x 4(N); warp tile 64x32; m16n8k16 fp16 mma, fp32 accum.
// 96 KB smem + 128 regs -> 2 CTAs/SM.
// Grid: x = M tiles (fast-varying, shares B tile), y = N tiles.
// ---------------------------------------------------------------------------
static constexpr int NSTAGES     = 3;
static constexpr int A_BYTES     = 128 * 128;          // 16 KB
static constexpr int B_BYTES     = 128 * 128;          // 16 KB
static constexpr int STAGE_BYTES = A_BYTES + B_BYTES;  // 32 KB
static constexpr int SMEM_DYN    = NSTAGES * STAGE_BYTES;   // 96 KB

__global__ __launch_bounds__(256, 2)
void gemm_fp16(const float* __restrict__ bias, float* __restrict__ out,
               int M, int N, int K) {
    extern __shared__ char smem[];
    const int tid = threadIdx.x;
    const int wid = tid >> 5;
    const int lane = tid & 31;
    const int m0 = blockIdx.x * 128;          // x -> M tiles (fast-varying)
    const int n0 = blockIdx.y * 128;          // y -> N tiles
    const uint32_t sbase = smem_u32(smem);

    const int warp_m = (wid & 1) * 64;
    const int warp_n = (wid >> 1) * 32;

    const int NUM_IT = K >> 6;                        // 16 k-tiles of 64

    // ---- async stage loader: 2048 16B-chunks over 256 threads x 8 ----------
    auto load_stage = [&](int slot, int it) {
        const uint32_t sb = sbase + slot * STAGE_BYTES;
        const int kt = it << 6;
#pragma unroll
        for (int i = 0; i < 8; i++) {
            int cid = tid + i * 256;                  // 0..2047
            int mat = cid >> 10;                      // 0:A 1:B
            int within = cid & 1023;
            int row = within >> 3;                    // 0..127
            int c16 = within & 7;
            const __half* src = (mat == 0)
                ? g_xp + (size_t)(m0 + row) * K + kt + c16 * 8
                : g_wp + (size_t)(n0 + row) * K + kt + c16 * 8;
            uint32_t off = (uint32_t)(row * 128 + c16 * 16);
            cp_async16(sb + mat * A_BYTES + sw128(off), src);
        }
        cp_async_commit();
    };

    load_stage(0, 0);
    load_stage(1, 1);

    float acc[4][4][4];
#pragma unroll
    for (int i = 0; i < 4; i++)
#pragma unroll
        for (int j = 0; j < 4; j++)
#pragma unroll
            for (int r = 0; r < 4; r++) acc[i][j][r] = 0.0f;

    const int a_row = lane & 15;
    const int a_kc  = ((lane >> 4) & 1) * 8;
    const int b_row = ((lane >> 4) & 1) * 8 + (lane & 7);
    const int b_kc  = ((lane >> 3) & 1) * 8;

    for (int it = 0; it < NUM_IT; it++) {
        const int s = it % NSTAGES;
        if (it < NUM_IT - 1) cp_async_wait<NSTAGES - 2>();
        else                 cp_async_wait<0>();
        __syncthreads();

        if (it + NSTAGES - 1 < NUM_IT)
            load_stage((it + NSTAGES - 1) % NSTAGES, it + NSTAGES - 1);

        const uint32_t sA = sbase + s * STAGE_BYTES;
        const uint32_t sB = sA + A_BYTES;

#pragma unroll
        for (int ks = 0; ks < 4; ks++) {
            uint32_t a[4][4], b[4][2];
#pragma unroll
            for (int mi = 0; mi < 4; mi++) {
                int row = warp_m + mi * 16 + a_row;
                uint32_t off = (uint32_t)(row * 128 + (ks * 16 + a_kc) * 2);
                ldsm_x4(a[mi], sA + sw128(off));
            }
#pragma unroll
            for (int p = 0; p < 2; p++) {
                int row = warp_n + p * 16 + b_row;
                uint32_t off = (uint32_t)(row * 128 + (ks * 16 + b_kc) * 2);
                uint32_t t[4];
                ldsm_x4(t, sB + sw128(off));
                b[p * 2 + 0][0] = t[0]; b[p * 2 + 0][1] = t[1];
                b[p * 2 + 1][0] = t[2]; b[p * 2 + 1][1] = t[3];
            }
#pragma unroll
            for (int mi = 0; mi < 4; mi++)
#pragma unroll
                for (int nj = 0; nj < 4; nj++)
                    mma_fp16(acc[mi][nj], a[mi], b[nj]);
        }
    }

    // ---- epilogue: bias + global writes ------------------------------------
    const int col_base = n0 + warp_n + 2 * (lane & 3);
    const int row_base = m0 + warp_m + (lane >> 2);

#pragma unroll
    for (int nj = 0; nj < 4; nj++) {
        int c = col_base + nj * 8;
        float b0 = __ldg(bias + c);
        float b1 = __ldg(bias + c + 1);
#pragma unroll
        for (int mi = 0; mi < 4; mi++) {
            int r = row_base + mi * 16;
            float2 v0 = make_float2(acc[mi][nj][0] + b0, acc[mi][nj][1] + b1);
            float2 v1 = make_float2(acc[mi][nj][2] + b0, acc[mi][nj][3] + b1);
            *(float2*)(out + (size_t)r * N + c) = v0;
            *(float2*)(out + (size_t)(r + 8) * N + c) = v1;
        }
    }
}

// ---------------------------------------------------------------------------
// Launch
// ---------------------------------------------------------------------------
extern "C" void kernel_launch(void* const* d_in, const int* in_sizes, int n_in,
                              void* d_out, int out_size) {
    const float* x    = (const float*)d_in[0];
    const float* w    = (const float*)d_in[1];
    const float* bias = (const float*)d_in[2];
    float* out = (float*)d_out;

    const int n_out = in_sizes[2];                        // 4096
    const int kd    = in_sizes[1] / n_out;                // 4096
    const int M     = (int)((long long)in_sizes[0] / kd); // 16384
    const int Kp    = kd / 4;                             // 1024

    cudaFuncSetAttribute(gemm_fp16,
                         cudaFuncAttributeMaxDynamicSharedMemorySize, SMEM_DYN);

    {
        long long total_x = (long long)M * (kd >> 3);
        long long total = total_x + (long long)n_out * (kd >> 3);
        pack_xw<<<(int)((total + 255) / 256), 256>>>(x, w, total_x, total, kd);
    }
    {
        dim3 grid(M / 128, n_out / 128);                  // x = M tiles, y = N tiles
        gemm_fp16<<<grid, 256, SMEM_DYN>>>(bias, out, M, n_out, Kp);
    }
}

// round 17
// speedup vs baseline: 1.3268x; 1.0624x over previous
#include <cuda_runtime.h>
#include <cuda_fp16.h>
#include <cstdint>
#include <cstddef>

// ---------------------------------------------------------------------------
// VenomSpmm: y = x @ (W * mask).T + bias, mask keeps k%8 in {0,2}.
// K 4096 -> 1024 packed fp16. Single-pass fp16 GEMM (fp32 accum) on mma.sync.
// Champion config (R14/R16, 415-417us): CTA 128x128, warp tile 64x32, BK=64,
// 3-stage inline cp.async ring, 96KB smem, launch_bounds(256,2) -> 2 CTAs/SM,
// M-fast rasterization. This round: outer loop unrolled by NSTAGES with
// compile-time consume/prefetch slot constants (no modulo in hot path).
// ---------------------------------------------------------------------------

static constexpr int MAX_M  = 16384;
static constexpr int MAX_N  = 4096;
static constexpr int MAX_KP = 1024;

__device__ __half g_xp[(size_t)MAX_M * MAX_KP];   // 32 MB
__device__ __half g_wp[(size_t)MAX_N * MAX_KP];   // 8 MB

// ---------------------------------------------------------------------------
// Combined pack kernel: keep positions 0,2 of every 8 along K, fp32->fp16.
// ---------------------------------------------------------------------------
__global__ void pack_xw(const float* __restrict__ xs, const float* __restrict__ ws,
                        long long total_x, long long total, int kd) {
    long long idx = (long long)blockIdx.x * blockDim.x + threadIdx.x;
    if (idx >= total) return;
    int gpr = kd >> 3;
    const float* src;
    __half* dst;
    long long lidx;
    if (idx < total_x) { src = xs; dst = g_xp; lidx = idx; }
    else               { src = ws; dst = g_wp; lidx = idx - total_x; }
    long long m = lidx / gpr;
    int g = (int)(lidx - m * (long long)gpr);
    const float* p = src + m * (long long)kd + ((long long)g << 3);
    __half2 h;
    h.x = __float2half(p[0]);
    h.y = __float2half(p[2]);
    *(__half2*)(dst + (size_t)m * (size_t)(kd >> 2) + 2 * (size_t)g) = h;
}

// ---------------------------------------------------------------------------
// PTX helpers (baseline ISA only — harness ptxas targets sm_103, no 'a')
// ---------------------------------------------------------------------------
__device__ __forceinline__ uint32_t smem_u32(const void* p) {
    uint32_t a;
    asm("{ .reg .u64 t; cvta.to.shared.u64 t, %1; cvt.u32.u64 %0, t; }"
        : "=r"(a) : "l"(p));
    return a;
}
__device__ __forceinline__ void cp_async16(uint32_t dst, const void* src) {
    asm volatile("cp.async.cg.shared.global [%0], [%1], 16;\n" :: "r"(dst), "l"(src));
}
__device__ __forceinline__ void cp_async_commit() {
    asm volatile("cp.async.commit_group;\n" ::: "memory");
}
template <int N>
__device__ __forceinline__ void cp_async_wait() {
    asm volatile("cp.async.wait_group %0;\n" :: "n"(N) : "memory");
}
__device__ __forceinline__ void ldsm_x4(uint32_t* r, uint32_t addr) {
    asm volatile("ldmatrix.sync.aligned.m8n8.x4.shared.b16 {%0,%1,%2,%3}, [%4];"
                 : "=r"(r[0]), "=r"(r[1]), "=r"(r[2]), "=r"(r[3]) : "r"(addr));
}
__device__ __forceinline__ void mma_fp16(float* d, const uint32_t* a, const uint32_t* b) {
    asm volatile(
        "mma.sync.aligned.m16n8k16.row.col.f32.f16.f16.f32 "
        "{%0,%1,%2,%3}, {%4,%5,%6,%7}, {%8,%9}, {%0,%1,%2,%3};\n"
        : "+f"(d[0]), "+f"(d[1]), "+f"(d[2]), "+f"(d[3])
        : "r"(a[0]), "r"(a[1]), "r"(a[2]), "r"(a[3]), "r"(b[0]), "r"(b[1]));
}
__device__ __forceinline__ uint32_t sw128(uint32_t off) {
    return off ^ ((off >> 3) & 0x70);
}

// ---------------------------------------------------------------------------
// GEMM: out[M,N] = A*B^T + bias,  A=g_xp[M,K], B=g_wp[N,K], K=1024 (fp16)
// CTA tile 128(M) x 128(N), BK=64 (128B rows, SW128), 3-stage cp.async ring.
// 8 warps as 2(M) x 4(N); warp tile 64x32; m16n8k16 fp16 mma, fp32 accum.
// 96 KB smem + 128 regs -> 2 CTAs/SM. Grid: x = M tiles (fast), y = N tiles.
// ---------------------------------------------------------------------------
static constexpr int NSTAGES     = 3;
static constexpr int A_BYTES     = 128 * 128;          // 16 KB
static constexpr int B_BYTES     = 128 * 128;          // 16 KB
static constexpr int STAGE_BYTES = A_BYTES + B_BYTES;  // 32 KB
static constexpr int SMEM_DYN    = NSTAGES * STAGE_BYTES;   // 96 KB

__global__ __launch_bounds__(256, 2)
void gemm_fp16(const float* __restrict__ bias, float* __restrict__ out,
               int M, int N, int K) {
    extern __shared__ char smem[];
    const int tid = threadIdx.x;
    const int wid = tid >> 5;
    const int lane = tid & 31;
    const int m0 = blockIdx.x * 128;          // x -> M tiles (fast-varying)
    const int n0 = blockIdx.y * 128;          // y -> N tiles
    const uint32_t sbase = smem_u32(smem);

    const int warp_m = (wid & 1) * 64;
    const int warp_n = (wid >> 1) * 32;

    const int NUM_IT = K >> 6;                        // 16 k-tiles of 64

    // ---- async stage loader: 2048 16B-chunks over 256 threads x 8 ----------
    auto load_stage = [&](int slot, int it) {
        const uint32_t sb = sbase + slot * STAGE_BYTES;
        const int kt = it << 6;
#pragma unroll
        for (int i = 0; i < 8; i++) {
            int cid = tid + i * 256;                  // 0..2047
            int mat = cid >> 10;                      // 0:A 1:B
            int within = cid & 1023;
            int row = within >> 3;                    // 0..127
            int c16 = within & 7;
            const __half* src = (mat == 0)
                ? g_xp + (size_t)(m0 + row) * K + kt + c16 * 8
                : g_wp + (size_t)(n0 + row) * K + kt + c16 * 8;
            uint32_t off = (uint32_t)(row * 128 + c16 * 16);
            cp_async16(sb + mat * A_BYTES + sw128(off), src);
        }
        cp_async_commit();
    };

    load_stage(0, 0);
    load_stage(1, 1);

    float acc[4][4][4];
#pragma unroll
    for (int i = 0; i < 4; i++)
#pragma unroll
        for (int j = 0; j < 4; j++)
#pragma unroll
            for (int r = 0; r < 4; r++) acc[i][j][r] = 0.0f;

    const int a_row = lane & 15;
    const int a_kc  = ((lane >> 4) & 1) * 8;
    const int b_row = ((lane >> 4) & 1) * 8 + (lane & 7);
    const int b_kc  = ((lane >> 3) & 1) * 8;

    // One pipeline iteration: consume `cslot`, prefetch it+2 into `pslot`.
    auto iter_body = [&](int cslot, int pslot, int it) {
        if (it < NUM_IT - 1) cp_async_wait<NSTAGES - 2>();
        else                 cp_async_wait<0>();
        __syncthreads();

        if (it + NSTAGES - 1 < NUM_IT)
            load_stage(pslot, it + NSTAGES - 1);

        const uint32_t sA = sbase + cslot * STAGE_BYTES;
        const uint32_t sB = sA + A_BYTES;

#pragma unroll
        for (int ks = 0; ks < 4; ks++) {
            uint32_t a[4][4], b[4][2];
#pragma unroll
            for (int mi = 0; mi < 4; mi++) {
                int row = warp_m + mi * 16 + a_row;
                uint32_t off = (uint32_t)(row * 128 + (ks * 16 + a_kc) * 2);
                ldsm_x4(a[mi], sA + sw128(off));
            }
#pragma unroll
            for (int p = 0; p < 2; p++) {
                int row = warp_n + p * 16 + b_row;
                uint32_t off = (uint32_t)(row * 128 + (ks * 16 + b_kc) * 2);
                uint32_t t[4];
                ldsm_x4(t, sB + sw128(off));
                b[p * 2 + 0][0] = t[0]; b[p * 2 + 0][1] = t[1];
                b[p * 2 + 1][0] = t[2]; b[p * 2 + 1][1] = t[3];
            }
#pragma unroll
            for (int mi = 0; mi < 4; mi++)
#pragma unroll
                for (int nj = 0; nj < 4; nj++)
                    mma_fp16(acc[mi][nj], a[mi], b[nj]);
        }
    };

    // Unrolled by NSTAGES: consume slot it%3, prefetch slot (it+2)%3 — both
    // compile-time constants in each copy. Tail handles NUM_IT % 3 != 0.
    int it = 0;
    for (; it + NSTAGES <= NUM_IT; it += NSTAGES) {
        iter_body(0, 2, it + 0);
        iter_body(1, 0, it + 1);
        iter_body(2, 1, it + 2);
    }
    for (; it < NUM_IT; it++)
        iter_body(it % NSTAGES, (it + 2) % NSTAGES, it);

    // ---- epilogue: bias + global writes ------------------------------------
    const int col_base = n0 + warp_n + 2 * (lane & 3);
    const int row_base = m0 + warp_m + (lane >> 2);

#pragma unroll
    for (int nj = 0; nj < 4; nj++) {
        int c = col_base + nj * 8;
        float b0 = __ldg(bias + c);
        float b1 = __ldg(bias + c + 1);
#pragma unroll
        for (int mi = 0; mi < 4; mi++) {
            int r = row_base + mi * 16;
            float2 v0 = make_float2(acc[mi][nj][0] + b0, acc[mi][nj][1] + b1);
            float2 v1 = make_float2(acc[mi][nj][2] + b0, acc[mi][nj][3] + b1);
            *(float2*)(out + (size_t)r * N + c) = v0;
            *(float2*)(out + (size_t)(r + 8) * N + c) = v1;
        }
    }
}

// ---------------------------------------------------------------------------
// Launch
// ---------------------------------------------------------------------------
extern "C" void kernel_launch(void* const* d_in, const int* in_sizes, int n_in,
                              void* d_out, int out_size) {
    const float* x    = (const float*)d_in[0];
    const float* w    = (const float*)d_in[1];
    const float* bias = (const float*)d_in[2];
    float* out = (float*)d_out;

    const int n_out = in_sizes[2];                        // 4096
    const int kd    = in_sizes[1] / n_out;                // 4096
    const int M     = (int)((long long)in_sizes[0] / kd); // 16384
    const int Kp    = kd / 4;                             // 1024

    cudaFuncSetAttribute(gemm_fp16,
                         cudaFuncAttributeMaxDynamicSharedMemorySize, SMEM_DYN);

    {
        long long total_x = (long long)M * (kd >> 3);
        long long total = total_x + (long long)n_out * (kd >> 3);
        pack_xw<<<(int)((total + 255) / 256), 256>>>(x, w, total_x, total, kd);
    }
    {
        dim3 grid(M / 128, n_out / 128);                  // x = M tiles, y = N tiles
        gemm_fp16<<<grid, 256, SMEM_DYN>>>(bias, out, M, n_out, Kp);
    }
}